// round 1
// baseline (speedup 1.0000x reference)
#include <cuda_runtime.h>
#include <cuda_bf16.h>
#include <math.h>

// ===========================================================================
// MS-SSIM for 16x3x512x512 fp32 pairs, 5 levels.
// Per level: fused separable 11x11 Gaussian conv (horizontal in SMEM,
// vertical in a register ring buffer) + per-pixel SSIM/CS + block reduce +
// atomicAdd into per-level double accumulators. Then 2x avg-pool.
// Final single-thread kernel combines the 10 accumulators.
// ===========================================================================

#define OC 128            // output columns per block (== threads)
#define ORR 32            // output rows per block
#define IR (ORR + 10)     // 42 input rows
#define ICW (OC + 10)     // 138 input cols

// Gaussian taps, sigma=1.5, ws=11 (normalized, double-accurate)
#define G0 0.00102838f
#define G1 0.00759876f
#define G2 0.03600077f
#define G3 0.10936069f
#define G4 0.21300553f
#define G5 0.26601172f

__device__ __constant__ float c_gauss_dummy = 0.f; // (taps are immediates below)

#define C1V 1.0e-4f
#define C2V 9.0e-4f

// Scratch for pooled pyramids (no cudaMalloc allowed)
#define S1 (48u * 256u * 256u)   // 3145728
#define S2 (48u * 128u * 128u)   // 786432
#define S3 (48u * 64u  * 64u)    // 196608
#define S4 (48u * 32u  * 32u)    // 49152
#define O1 0u
#define O2 (S1)
#define O3 (S1 + S2)
#define O4 (S1 + S2 + S3)
#define TOT (S1 + S2 + S3 + S4)

__device__ float g_p1[TOT];
__device__ float g_p2[TOT];
__device__ double g_acc[10];   // [2*l] = sum(ssim_map), [2*l+1] = sum(cs_map)

__global__ void zero_acc_kernel() {
    if (threadIdx.x < 10) g_acc[threadIdx.x] = 0.0;
}

__global__ void __launch_bounds__(OC)
ssim_level_kernel(const float* __restrict__ A, const float* __restrict__ B,
                  int H, int level) {
    __shared__ float sA[IR * ICW];
    __shared__ float sB[IR * ICW];

    const int tid = threadIdx.x;
    const int rowBase = blockIdx.y * ORR;
    const int colBase = blockIdx.x * OC;
    const int W = H;
    const size_t zoff = (size_t)blockIdx.z * H * W;
    const float* __restrict__ Ap = A + zoff;
    const float* __restrict__ Bp = B + zoff;

    // ---- load input tile (with boundary clamp to 0; those lanes never
    // contribute to a valid output) ----
    for (int i = tid; i < IR * ICW; i += OC) {
        int r = i / ICW;
        int c = i - r * ICW;
        int gr = rowBase + r, gc = colBase + c;
        float a = 0.f, b = 0.f;
        if (gr < H && gc < W) {
            a = __ldg(Ap + (size_t)gr * W + gc);
            b = __ldg(Bp + (size_t)gr * W + gc);
        }
        sA[i] = a;
        sB[i] = b;
    }
    __syncthreads();

    const int oc = colBase + tid;
    const bool col_ok = oc < (W - 10);

    const float G[11] = {G0, G1, G2, G3, G4, G5, G4, G3, G2, G1, G0};

    // register ring buffers for horizontally-convolved rows
    float h1[11], h2[11], h11[11], h22[11], h12[11];
    float accS = 0.f, accC = 0.f;

    #pragma unroll
    for (int r = 0; r < IR; r++) {
        // ---- horizontal pass for this input row ----
        float s1 = 0.f, s2 = 0.f, p11 = 0.f, p22 = 0.f, p12 = 0.f;
        #pragma unroll
        for (int k = 0; k < 11; k++) {
            float va = sA[r * ICW + tid + k];
            float vb = sB[r * ICW + tid + k];
            float g  = G[k];
            float va2 = va * va;
            float vb2 = vb * vb;
            float vab = va * vb;
            s1  += g * va;
            s2  += g * vb;
            p11 += g * va2;
            p22 += g * vb2;
            p12 += g * vab;
        }
        const int slot = r % 11;               // compile-time (fully unrolled)
        h1[slot] = s1; h2[slot] = s2; h11[slot] = p11; h22[slot] = p22; h12[slot] = p12;

        // ---- vertical pass once the ring is full ----
        if (r >= 10) {
            float m1 = 0.f, m2 = 0.f, m11 = 0.f, m22 = 0.f, m12 = 0.f;
            #pragma unroll
            for (int j = 0; j < 11; j++) {
                const int sl = (r - 10 + j) % 11;  // compile-time
                float g = G[j];
                m1  += g * h1[sl];
                m2  += g * h2[sl];
                m11 += g * h11[sl];
                m22 += g * h22[sl];
                m12 += g * h12[sl];
            }
            int gr = rowBase + r;
            if (col_ok && gr < H) {
                float mu11 = m1 * m1;
                float mu22 = m2 * m2;
                float mu12 = m1 * m2;
                float sig1  = m11 - mu11;
                float sig2  = m22 - mu22;
                float sig12 = m12 - mu12;
                float v1 = 2.f * sig12 + C2V;
                float v2 = sig1 + sig2 + C2V;
                float cs = __fdividef(v1, v2);
                float ssim = __fdividef((2.f * mu12 + C1V) * v1,
                                        (mu11 + mu22 + C1V) * v2);
                accS += ssim;
                accC += cs;
            }
        }
    }

    // ---- block reduction ----
    #pragma unroll
    for (int off = 16; off > 0; off >>= 1) {
        accS += __shfl_down_sync(0xFFFFFFFFu, accS, off);
        accC += __shfl_down_sync(0xFFFFFFFFu, accC, off);
    }
    __shared__ float wS[OC / 32], wC[OC / 32];
    const int warp = tid >> 5, lane = tid & 31;
    if (lane == 0) { wS[warp] = accS; wC[warp] = accC; }
    __syncthreads();
    if (tid == 0) {
        float bs = 0.f, bc = 0.f;
        #pragma unroll
        for (int wi = 0; wi < OC / 32; wi++) { bs += wS[wi]; bc += wC[wi]; }
        atomicAdd(&g_acc[2 * level],     (double)bs);
        atomicAdd(&g_acc[2 * level + 1], (double)bc);
    }
}

__global__ void pool_kernel(const float* __restrict__ src, float* __restrict__ dst,
                            int Hs, int total) {
    int idx = blockIdx.x * blockDim.x + threadIdx.x;
    if (idx >= total) return;
    int Ws = Hs;
    int Wo = Ws >> 1, Ho = Hs >> 1;
    int x = idx % Wo;
    int t = idx / Wo;
    int y = t % Ho;
    int z = t / Ho;
    const float* p = src + ((size_t)z * Hs + 2 * y) * Ws + 2 * x;
    float v = p[0] + p[1] + p[Ws] + p[Ws + 1];
    dst[idx] = 0.25f * v;
}

__global__ void final_kernel(float* __restrict__ out) {
    const double Hl[5]  = {502.0, 246.0, 118.0, 54.0, 22.0};
    const double Wt[5]  = {0.0448, 0.2856, 0.3001, 0.2363, 0.1333};
    double prod = 1.0;
    double ms4 = 0.0;
    for (int l = 0; l < 5; l++) {
        double cnt = 48.0 * Hl[l] * Hl[l];
        double ms = (g_acc[2 * l]     / cnt + 1.0) * 0.5;
        double mc = (g_acc[2 * l + 1] / cnt + 1.0) * 0.5;
        if (l < 4) prod *= pow(mc, Wt[l]);
        else       ms4 = pow(ms, Wt[4]);
    }
    // reference: prod(pow1[:-1] * pow2[-1]) -> pow2[-1] enters 4 times
    prod *= ms4 * ms4 * ms4 * ms4;
    out[0] = (float)prod;
}

static inline void launch_level(const float* a, const float* b, int H, int level) {
    int outw = H - 10;
    dim3 grid((outw + OC - 1) / OC, (outw + ORR - 1) / ORR, 48);
    ssim_level_kernel<<<grid, OC>>>(a, b, H, level);
}

extern "C" void kernel_launch(void* const* d_in, const int* in_sizes, int n_in,
                              void* d_out, int out_size) {
    const float* img1 = (const float*)d_in[0];
    const float* img2 = (const float*)d_in[1];
    float* out = (float*)d_out;

    float* p1; float* p2;
    cudaGetSymbolAddress((void**)&p1, g_p1);
    cudaGetSymbolAddress((void**)&p2, g_p2);

    zero_acc_kernel<<<1, 32>>>();

    // Level 0 (512)
    launch_level(img1, img2, 512, 0);
    {
        int total = (int)S1;
        int blocks = (total + 255) / 256;
        pool_kernel<<<blocks, 256>>>(img1, p1 + O1, 512, total);
        pool_kernel<<<blocks, 256>>>(img2, p2 + O1, 512, total);
    }
    // Level 1 (256)
    launch_level(p1 + O1, p2 + O1, 256, 1);
    {
        int total = (int)S2;
        int blocks = (total + 255) / 256;
        pool_kernel<<<blocks, 256>>>(p1 + O1, p1 + O2, 256, total);
        pool_kernel<<<blocks, 256>>>(p2 + O1, p2 + O2, 256, total);
    }
    // Level 2 (128)
    launch_level(p1 + O2, p2 + O2, 128, 2);
    {
        int total = (int)S3;
        int blocks = (total + 255) / 256;
        pool_kernel<<<blocks, 256>>>(p1 + O2, p1 + O3, 128, total);
        pool_kernel<<<blocks, 256>>>(p2 + O2, p2 + O3, 128, total);
    }
    // Level 3 (64)
    launch_level(p1 + O3, p2 + O3, 64, 3);
    {
        int total = (int)S4;
        int blocks = (total + 255) / 256;
        pool_kernel<<<blocks, 256>>>(p1 + O3, p1 + O4, 64, total);
        pool_kernel<<<blocks, 256>>>(p2 + O3, p2 + O4, 64, total);
    }
    // Level 4 (32)
    launch_level(p1 + O4, p2 + O4, 32, 4);

    final_kernel<<<1, 1>>>(out);
}

// round 2
// speedup vs baseline: 1.3293x; 1.3293x over previous
#include <cuda_runtime.h>
#include <cuda_bf16.h>
#include <math.h>

// ===========================================================================
// MS-SSIM 16x3x512x512 fp32, 5 levels.
// ssim_level_kernel: separable 11x11 Gaussian conv, A/B interleaved float2 in
// SMEM, f32x2-packed FMA math (PTX fma.rn.f32x2), register ring buffer for
// the vertical pass, per-pixel SSIM/CS, block reduce, atomicAdd to doubles.
// pool2_kernel: fused 2x avg-pool of BOTH images, float4 loads.
// ===========================================================================

#define OC 128            // output columns per block (== threads)
#define ORR 32            // output rows per block
#define IR (ORR + 10)     // 42 input rows
#define ICW (OC + 10)     // 138 input cols

// Gaussian taps, sigma=1.5, ws=11
#define G0 0.00102838f
#define G1 0.00759876f
#define G2 0.03600077f
#define G3 0.10936069f
#define G4 0.21300553f
#define G5 0.26601172f

#define C1V 1.0e-4f
#define C2V 9.0e-4f

// Scratch for pooled pyramids
#define S1 (48u * 256u * 256u)
#define S2 (48u * 128u * 128u)
#define S3 (48u * 64u  * 64u)
#define S4 (48u * 32u  * 32u)
#define O1 0u
#define O2 (S1)
#define O3 (S1 + S2)
#define O4 (S1 + S2 + S3)
#define TOT (S1 + S2 + S3 + S4)

__device__ float g_p1[TOT];
__device__ float g_p2[TOT];
__device__ double g_acc[10];

// ---- f32x2 packed helpers -------------------------------------------------
__device__ __forceinline__ unsigned long long pk2(float lo, float hi) {
    unsigned long long r;
    asm("mov.b64 %0, {%1, %2};" : "=l"(r) : "f"(lo), "f"(hi));
    return r;
}
__device__ __forceinline__ void upk2(unsigned long long v, float& lo, float& hi) {
    asm("mov.b64 {%0, %1}, %2;" : "=f"(lo), "=f"(hi) : "l"(v));
}
__device__ __forceinline__ unsigned long long fma2(unsigned long long a,
                                                   unsigned long long b,
                                                   unsigned long long c) {
    unsigned long long d;
    asm("fma.rn.f32x2 %0, %1, %2, %3;" : "=l"(d) : "l"(a), "l"(b), "l"(c));
    return d;
}
__device__ __forceinline__ unsigned long long mul2(unsigned long long a,
                                                   unsigned long long b) {
    unsigned long long d;
    asm("mul.rn.f32x2 %0, %1, %2;" : "=l"(d) : "l"(a), "l"(b));
    return d;
}

__global__ void zero_acc_kernel() {
    if (threadIdx.x < 10) g_acc[threadIdx.x] = 0.0;
}

__global__ void __launch_bounds__(OC)
ssim_level_kernel(const float* __restrict__ A, const float* __restrict__ B,
                  int H, int level) {
    __shared__ float2 sAB[IR * ICW];

    const int tid = threadIdx.x;
    const int rowBase = blockIdx.y * ORR;
    const int colBase = blockIdx.x * OC;
    const int W = H;
    const size_t zoff = (size_t)blockIdx.z * H * W;
    const float* __restrict__ Ap = A + zoff;
    const float* __restrict__ Bp = B + zoff;

    // ---- load interleaved tile (zero-clamped halo; masked outputs) ----
    for (int i = tid; i < IR * ICW; i += OC) {
        int r = i / ICW;
        int c = i - r * ICW;
        int gr = rowBase + r, gc = colBase + c;
        float a = 0.f, b = 0.f;
        if (gr < H && gc < W) {
            size_t o = (size_t)gr * W + gc;
            a = __ldg(Ap + o);
            b = __ldg(Bp + o);
        }
        sAB[i] = make_float2(a, b);
    }
    __syncthreads();

    const int oc = colBase + tid;
    const bool col_ok = oc < (W - 10);

    const float Gf[11] = {G0, G1, G2, G3, G4, G5, G4, G3, G2, G1, G0};
    unsigned long long Gp[11];
    #pragma unroll
    for (int k = 0; k < 11; k++) Gp[k] = pk2(Gf[k], Gf[k]);

    // register rings: packed (mu1,mu2), packed (x^2,y^2), scalar (x*y)
    unsigned long long rMu[11], rPP[11];
    float rXY[11];
    float accS = 0.f, accC = 0.f;

    #pragma unroll
    for (int r = 0; r < IR; r++) {
        // ---- horizontal pass ----
        unsigned long long s12   = pk2(0.f, 0.f);
        unsigned long long s1122 = pk2(0.f, 0.f);
        float p12 = 0.f;
        const float2* __restrict__ rowp = &sAB[r * ICW + tid];
        #pragma unroll
        for (int k = 0; k < 11; k++) {
            float2 v = rowp[k];                       // LDS.64
            unsigned long long vp = pk2(v.x, v.y);
            unsigned long long vv = mul2(vp, vp);     // (a^2, b^2)
            float vab = v.x * v.y;
            s12   = fma2(vp, Gp[k], s12);
            s1122 = fma2(vv, Gp[k], s1122);
            p12   = fmaf(vab, Gf[k], p12);
        }
        const int slot = r % 11;                      // compile-time
        rMu[slot] = s12; rPP[slot] = s1122; rXY[slot] = p12;

        // ---- vertical pass ----
        if (r >= 10) {
            unsigned long long m12   = pk2(0.f, 0.f);
            unsigned long long m1122 = pk2(0.f, 0.f);
            float mxy = 0.f;
            #pragma unroll
            for (int j = 0; j < 11; j++) {
                const int sl = (r - 10 + j) % 11;     // compile-time
                m12   = fma2(rMu[sl], Gp[j], m12);
                m1122 = fma2(rPP[sl], Gp[j], m1122);
                mxy   = fmaf(rXY[sl], Gf[j], mxy);
            }
            int gr = rowBase + r;
            if (col_ok && gr < H) {
                float m1, m2, s11, s22;
                upk2(m12, m1, m2);
                upk2(m1122, s11, s22);
                float mu11 = m1 * m1;
                float mu22 = m2 * m2;
                float mu12 = m1 * m2;
                float sig1  = s11 - mu11;
                float sig2  = s22 - mu22;
                float sig12 = mxy - mu12;
                float v1 = 2.f * sig12 + C2V;
                float v2 = sig1 + sig2 + C2V;
                float cs = __fdividef(v1, v2);
                float ssim = cs * __fdividef(2.f * mu12 + C1V, mu11 + mu22 + C1V);
                accS += ssim;
                accC += cs;
            }
        }
    }

    // ---- block reduction ----
    #pragma unroll
    for (int off = 16; off > 0; off >>= 1) {
        accS += __shfl_down_sync(0xFFFFFFFFu, accS, off);
        accC += __shfl_down_sync(0xFFFFFFFFu, accC, off);
    }
    __shared__ float wS[OC / 32], wC[OC / 32];
    const int warp = tid >> 5, lane = tid & 31;
    if (lane == 0) { wS[warp] = accS; wC[warp] = accC; }
    __syncthreads();
    if (tid == 0) {
        float bs = 0.f, bc = 0.f;
        #pragma unroll
        for (int wi = 0; wi < OC / 32; wi++) { bs += wS[wi]; bc += wC[wi]; }
        atomicAdd(&g_acc[2 * level],     (double)bs);
        atomicAdd(&g_acc[2 * level + 1], (double)bc);
    }
}

// Fused 2x avg-pool of both images; float4 loads, float2 stores; shift math.
__global__ void pool2_kernel(const float* __restrict__ s1, const float* __restrict__ s2,
                             float* __restrict__ d1, float* __restrict__ d2,
                             int logWs, int total2) {
    int idx = blockIdx.x * blockDim.x + threadIdx.x;
    if (idx >= total2) return;
    const int whalf_bits = logWs - 2;                 // log2(Wo/2)
    const int ho_bits    = logWs - 1;                 // log2(Ho)
    int xp = idx & ((1 << whalf_bits) - 1);
    int t  = idx >> whalf_bits;
    int y  = t & ((1 << ho_bits) - 1);
    int z  = t >> ho_bits;
    size_t off = (((size_t)((z << logWs) + (y << 1))) << logWs) + ((size_t)xp << 2);
    int Ws = 1 << logWs;

    float4 a0 = *(const float4*)(s1 + off);
    float4 a1 = *(const float4*)(s1 + off + Ws);
    float4 b0 = *(const float4*)(s2 + off);
    float4 b1 = *(const float4*)(s2 + off + Ws);

    float2 oa = make_float2(0.25f * (a0.x + a0.y + a1.x + a1.y),
                            0.25f * (a0.z + a0.w + a1.z + a1.w));
    float2 ob = make_float2(0.25f * (b0.x + b0.y + b1.x + b1.y),
                            0.25f * (b0.z + b0.w + b1.z + b1.w));
    ((float2*)d1)[idx] = oa;
    ((float2*)d2)[idx] = ob;
}

__global__ void final_kernel(float* __restrict__ out) {
    const double Hl[5] = {502.0, 246.0, 118.0, 54.0, 22.0};
    const double Wt[5] = {0.0448, 0.2856, 0.3001, 0.2363, 0.1333};
    double prod = 1.0;
    double ms4 = 0.0;
    for (int l = 0; l < 5; l++) {
        double cnt = 48.0 * Hl[l] * Hl[l];
        double ms = (g_acc[2 * l]     / cnt + 1.0) * 0.5;
        double mc = (g_acc[2 * l + 1] / cnt + 1.0) * 0.5;
        if (l < 4) prod *= pow(mc, Wt[l]);
        else       ms4 = pow(ms, Wt[4]);
    }
    prod *= ms4 * ms4 * ms4 * ms4;   // pow2[-1] enters all 4 product terms
    out[0] = (float)prod;
}

static inline void launch_level(const float* a, const float* b, int H, int level) {
    int outw = H - 10;
    dim3 grid((outw + OC - 1) / OC, (outw + ORR - 1) / ORR, 48);
    ssim_level_kernel<<<grid, OC>>>(a, b, H, level);
}

static inline void launch_pool(const float* s1, const float* s2,
                               float* d1, float* d2, int logWs) {
    int Ws = 1 << logWs;
    int total2 = 48 * (Ws >> 1) * (Ws >> 2);   // outputs as float2
    pool2_kernel<<<(total2 + 255) / 256, 256>>>(s1, s2, d1, d2, logWs, total2);
}

extern "C" void kernel_launch(void* const* d_in, const int* in_sizes, int n_in,
                              void* d_out, int out_size) {
    const float* img1 = (const float*)d_in[0];
    const float* img2 = (const float*)d_in[1];
    float* out = (float*)d_out;

    float* p1; float* p2;
    cudaGetSymbolAddress((void**)&p1, g_p1);
    cudaGetSymbolAddress((void**)&p2, g_p2);

    zero_acc_kernel<<<1, 32>>>();

    launch_level(img1, img2, 512, 0);
    launch_pool(img1, img2, p1 + O1, p2 + O1, 9);

    launch_level(p1 + O1, p2 + O1, 256, 1);
    launch_pool(p1 + O1, p2 + O1, p1 + O2, p2 + O2, 8);

    launch_level(p1 + O2, p2 + O2, 128, 2);
    launch_pool(p1 + O2, p2 + O2, p1 + O3, p2 + O3, 7);

    launch_level(p1 + O3, p2 + O3, 64, 3);
    launch_pool(p1 + O3, p2 + O3, p1 + O4, p2 + O4, 6);

    launch_level(p1 + O4, p2 + O4, 32, 4);

    final_kernel<<<1, 1>>>(out);
}